// round 8
// baseline (speedup 1.0000x reference)
#include <cuda_runtime.h>
#include <cuda_fp16.h>
#include <math.h>

// ---------------- problem constants ----------------
#define XNE   100000
#define XB    8192
#define XCOLS 406
#define NITEMS (2*XB)

typedef unsigned long long ull;
typedef long long ll;

// ---------------- device scratch (no allocations allowed) ----------------
__device__ int g_xflag;                                    // 1 = x is int64, 0 = int32
__device__ __align__(16) __half g_tab_h[1000 * 256];       // [t][d]: d<128 cos(t*f[d]), d>=128 sin(t*f[d-128])
__device__ __align__(16) float  g_wp[512 * 256];           // folded e_p_emb weight W'
__device__ __align__(16) float  g_srel[(size_t)NITEMS * 256]; // s_rel / o_rel rows (P then +R)

// ---------------- helpers ----------------
__device__ __forceinline__ ll xval(const void* x, int f64, ll i) {
    return f64 ? ((const ll*)x)[i] : (ll)((const int*)x)[i];
}

// ---------------- K_prep: fused (tab | wp | detect) ----------------
// blocks 0..499    : positional table, 2 t-rows per block (256 threads)
// blocks 500..1011 : W' fold, k = blk-500 (256 threads)
// block  1012      : x element-width probe (thread 0)
__global__ __launch_bounds__(256) void k_prep(const void* __restrict__ x,
                                              const float* __restrict__ w_e) {
    int blk = blockIdx.x;
    int tid = threadIdx.x;

    if (blk < 500) {
        // pos_emb table: t = blk*2 + (tid>=128), j = tid&127, fp16 storage.
        // Accurate sincosf here (one-time build; feeds 0.84G FMA terms).
        int t = blk * 2 + (tid >> 7);
        int j = tid & 127;
        float ex = (float)(2 * j) / 256.0f;
        float f  = 1.0f / powf(10000.0f, ex);
        float rs = (float)t * f;
        float sv, cv;
        sincosf(rs, &sv, &cv);
        g_tab_h[t * 256 + j]       = __float2half_rn(cv);
        g_tab_h[t * 256 + 128 + j] = __float2half_rn(sv);
    } else if (blk < 1012) {
        // fold e_p_emb's 4 sign-structured sub-matmuls into W'(512x256):
        // j<128 : re_p = re_e@re_w - im_e@im_w
        // j>=128: im_p = im_e@re_w - re_e@im_w
        int k = blk - 500;            // 0..511
        int j = tid;                  // 0..255
        float v;
        if (j < 128) {
            v = w_e[k * 128 + j];
            if (k >= 256) v = -v;
        } else {
            int j2 = j - 128;
            if (k < 256) v = -w_e[(k + 256) * 128 + j2];
            else         v =  w_e[(k - 256) * 128 + j2];
        }
        g_wp[k * 256 + j] = v;
    } else if (tid == 0) {
        // int64-vs-int32 probe: all 406 ll-reads in range only if genuinely i64
        const ll* x64 = (const ll*)x;
        int ok = 1;
        for (int i = 0; i < XCOLS; i++) {
            ll v = x64[i];
            if (v < 0 || v >= 100000) { ok = 0; break; }
        }
        g_xflag = ok;
    }
}

// ---------------- K3: P = E_gather(16384x512) @ W'(512x256), FFMA2 ----------------
// CTA: 64 rows x 256 cols, 256 threads, per-thread 8x8 via packed f32x2 FMA.
__global__ __launch_bounds__(256, 2) void k_gemm(const void* __restrict__ x,
                                                 const float* __restrict__ e_emb) {
    __shared__ __align__(16) ull   Asd[16][66];   // A value duplicated (a,a), padded
    __shared__ __align__(16) float Bs[16][256];
    __shared__ int eidx[64];

    int tid = threadIdx.x;
    int m0  = blockIdx.x * 64;
    if (tid < 64) {
        int item = m0 + tid;
        int b = item >> 1;
        int f64 = g_xflag;
        eidx[tid] = (int)xval(x, f64, (ll)b * XCOLS + ((item & 1) ? 2 : 0));
    }
    __syncthreads();

    int ty = tid >> 5, tx = tid & 31;
    ull acc[8][4];
    #pragma unroll
    for (int r = 0; r < 8; r++)
        #pragma unroll
        for (int c = 0; c < 4; c++) acc[r][c] = 0ULL;

    int arow = tid >> 2, acg = (tid & 3) << 2;
    const float* asrc = e_emb + (size_t)eidx[arow] * 512 + acg;
    int bkr = tid >> 4, bcol = (tid & 15) << 4;

    for (int k0 = 0; k0 < 512; k0 += 16) {
        float4 av = *(const float4*)(asrc + k0);
        ull p0, p1, p2, p3;
        asm("mov.b64 %0, {%1,%1};" : "=l"(p0) : "f"(av.x));
        asm("mov.b64 %0, {%1,%1};" : "=l"(p1) : "f"(av.y));
        asm("mov.b64 %0, {%1,%1};" : "=l"(p2) : "f"(av.z));
        asm("mov.b64 %0, {%1,%1};" : "=l"(p3) : "f"(av.w));
        Asd[acg + 0][arow] = p0; Asd[acg + 1][arow] = p1;
        Asd[acg + 2][arow] = p2; Asd[acg + 3][arow] = p3;

        const float* bsrc = g_wp + (size_t)(k0 + bkr) * 256 + bcol;
        *(float4*)&Bs[bkr][bcol + 0]  = *(const float4*)(bsrc + 0);
        *(float4*)&Bs[bkr][bcol + 4]  = *(const float4*)(bsrc + 4);
        *(float4*)&Bs[bkr][bcol + 8]  = *(const float4*)(bsrc + 8);
        *(float4*)&Bs[bkr][bcol + 12] = *(const float4*)(bsrc + 12);
        __syncthreads();

        #pragma unroll
        for (int kk = 0; kk < 16; kk++) {
            ulonglong2 a01 = *(const ulonglong2*)&Asd[kk][ty * 8 + 0];
            ulonglong2 a23 = *(const ulonglong2*)&Asd[kk][ty * 8 + 2];
            ulonglong2 a45 = *(const ulonglong2*)&Asd[kk][ty * 8 + 4];
            ulonglong2 a67 = *(const ulonglong2*)&Asd[kk][ty * 8 + 6];
            ulonglong2 b01 = *(const ulonglong2*)&Bs[kk][tx * 4];
            ulonglong2 b23 = *(const ulonglong2*)&Bs[kk][128 + tx * 4];
            ull a_[8] = {a01.x, a01.y, a23.x, a23.y, a45.x, a45.y, a67.x, a67.y};
            ull b_[4] = {b01.x, b01.y, b23.x, b23.y};
            #pragma unroll
            for (int r = 0; r < 8; r++)
                #pragma unroll
                for (int c = 0; c < 4; c++)
                    asm("fma.rn.f32x2 %0, %1, %2, %0;"
                        : "+l"(acc[r][c]) : "l"(a_[r]), "l"(b_[c]));
        }
        __syncthreads();
    }

    #pragma unroll
    for (int r = 0; r < 8; r++) {
        float y0, y1, y2, y3;
        asm("mov.b64 {%0,%1}, %2;" : "=f"(y0), "=f"(y1) : "l"(acc[r][0]));
        asm("mov.b64 {%0,%1}, %2;" : "=f"(y2), "=f"(y3) : "l"(acc[r][1]));
        float* dst = g_srel + (size_t)(m0 + ty * 8 + r) * 256 + tx * 4;
        *(float4*)dst = make_float4(y0, y1, y2, y3);
        asm("mov.b64 {%0,%1}, %2;" : "=f"(y0), "=f"(y1) : "l"(acc[r][2]));
        asm("mov.b64 {%0,%1}, %2;" : "=f"(y2), "=f"(y3) : "l"(acc[r][3]));
        *(float4*)(dst + 128) = make_float4(y0, y1, y2, y3);
    }
}

// ---------------- K4: g_srel += C @ TAB (200-term table combination) ----------------
// Grid (256, 4): 64 items x 64-d slice per CTA (two 32-item batches over one
// staged table slice — 2x staging reuse). Table slice in smem as fp16, row
// stride 72 halves (144B): each LDS.128 quarter-warp phase reads 128
// contiguous bytes = all 32 banks once (conflict-free).
#define R_SMEM (144000 + 25600 + 51200)
__global__ __launch_bounds__(256) void k_rel(const void* __restrict__ x,
                                             const float* __restrict__ w_rp) {
    extern __shared__ __align__(16) char sm4[];
    __half* tab_s = (__half*)sm4;                       // 1000 x 72 halves
    short*  cidx  = (short*)(sm4 + 144000);             // 64 x 200
    float*  wv    = (float*)(sm4 + 144000 + 25600);     // 64 x 200
    __shared__ int ritem[64];

    int tid = threadIdx.x;
    int f64 = g_xflag;
    int i0  = blockIdx.x * 64;
    int d0  = blockIdx.y * 64;

    // stage table slice [1000 x 64] halves
    for (int idx = tid; idx < 8000; idx += 256) {
        int row = idx >> 3, seg = idx & 7;
        *(uint4*)(tab_s + row * 72 + seg * 8) =
            *(const uint4*)(g_tab_h + row * 256 + d0 + seg * 8);
    }
    if (tid < 64) {
        int item = i0 + tid;
        ritem[tid] = (int)xval(x, f64, (ll)(item >> 1) * XCOLS + 1);
    }
    __syncthreads();

    // stage per-item (t, w) coefficient lists
    for (int idx = tid; idx < 12800; idx += 256) {
        int it = idx / 200, n = idx - it * 200;
        int item = i0 + it;
        int b = item >> 1, side = item & 1;
        cidx[idx] = (short)xval(x, f64, (ll)b * XCOLS + 6 + side * 200 + n);
        wv[idx]   = w_rp[ritem[it] * 200 + n];
    }
    __syncthreads();

    int lane = tid & 31, w = tid >> 5;
    int dg = lane & 7;                      // 8 d's per lane
    const __half* tb = tab_s + dg * 8;

    #pragma unroll
    for (int ib = 0; ib < 2; ib++) {
        int item = ib * 32 + w * 4 + (lane >> 3);   // 0..63
        const short* cp  = cidx + item * 200;
        const float* wvp = wv   + item * 200;

        float acc[8] = {0.f, 0.f, 0.f, 0.f, 0.f, 0.f, 0.f, 0.f};
        #pragma unroll 4
        for (int n = 0; n < 200; n++) {
            int   t  = cp[n];
            float wn = wvp[n];
            uint4 h  = *(const uint4*)(tb + (size_t)t * 72);
            float2 v0 = __half22float2(*(__half2*)&h.x);
            float2 v1 = __half22float2(*(__half2*)&h.y);
            float2 v2 = __half22float2(*(__half2*)&h.z);
            float2 v3 = __half22float2(*(__half2*)&h.w);
            acc[0] = fmaf(v0.x, wn, acc[0]); acc[1] = fmaf(v0.y, wn, acc[1]);
            acc[2] = fmaf(v1.x, wn, acc[2]); acc[3] = fmaf(v1.y, wn, acc[3]);
            acc[4] = fmaf(v2.x, wn, acc[4]); acc[5] = fmaf(v2.y, wn, acc[5]);
            acc[6] = fmaf(v3.x, wn, acc[6]); acc[7] = fmaf(v3.y, wn, acc[7]);
        }

        float* dst = g_srel + (size_t)(i0 + item) * 256 + d0 + dg * 8;
        float4 o0 = *(float4*)dst;
        o0.x += acc[0]; o0.y += acc[1]; o0.z += acc[2]; o0.w += acc[3];
        *(float4*)dst = o0;
        float4 o1 = *(float4*)(dst + 4);
        o1.x += acc[4]; o1.y += acc[5]; o1.z += acc[6]; o1.w += acc[7];
        *(float4*)(dst + 4) = o1;
    }
}

// ---------------- K5: epilogue — sc_abs (with inline t_emb) + sc_rel ----------------
// Trig via MUFU intrinsics (__sincosf/__cosf/__sinf): all args |x| <~ 3, where
// intrinsic abs error ~5e-7 — negligible vs the 1e-3 gate. This guards against
// the harness compiling WITHOUT --use_fast_math (software sincosf would cost
// ~40 instr x 11.5M calls ~ 300+ us).
__global__ __launch_bounds__(256) void k_epi(const void* __restrict__ x,
        const float* __restrict__ e_emb, const float* __restrict__ r_emb,
        const float* __restrict__ d_frq, const float* __restrict__ d_phi,
        const float* __restrict__ d_amp, const float* __restrict__ m_frq,
        const float* __restrict__ m_phi, const float* __restrict__ m_amp,
        float* __restrict__ out) {
    int lane = threadIdx.x & 31;
    int b = blockIdx.x * 8 + (threadIdx.x >> 5);
    int f64 = g_xflag;
    ll base = (ll)b * XCOLS;
    int s = (int)xval(x, f64, base + 0);
    int r = (int)xval(x, f64, base + 1);
    int o = (int)xval(x, f64, base + 2);
    float dab = (float)xval(x, f64, base + 3);
    float mab = (float)xval(x, f64, base + 4);

    // EMB_RNG_R / PI, matching reference precision path
    float divc = (float)(sqrt(6.0 / 584.0) / 3.141592653589793);

    const float* es = e_emb + (size_t)s * 512;
    const float* eo = e_emb + (size_t)o * 512;
    const float* rr = r_emb + (size_t)r * 384;

    float sum = 0.f;

    // sc_abs, dd < 256: pure embedding part
    #pragma unroll
    for (int i = 0; i < 8; i++) {
        int dd = lane + 32 * i;
        float res = es[dd], ims = es[256 + dd];
        float reo = eo[dd], imo = eo[256 + dd];
        float cr, sr;
        __sincosf(rr[dd] / divc, &sr, &cr);
        float ra = res * cr - ims * sr - reo;
        float ia = res * sr + ims * cr - imo;
        sum += sqrtf(ra * ra + ia * ia);
    }

    // sc_abs, dd >= 256: t_emb part (d/m oscillators)
    const float* dfs = d_frq + (size_t)s * 256; const float* dps = d_phi + (size_t)s * 256;
    const float* das = d_amp + (size_t)s * 128;
    const float* mfs = m_frq + (size_t)s * 256; const float* mps = m_phi + (size_t)s * 256;
    const float* mas = m_amp + (size_t)s * 128;
    const float* dfo = d_frq + (size_t)o * 256; const float* dpo = d_phi + (size_t)o * 256;
    const float* dao = d_amp + (size_t)o * 128;
    const float* mfo = m_frq + (size_t)o * 256; const float* mpo = m_phi + (size_t)o * 256;
    const float* mao = m_amp + (size_t)o * 128;
    #pragma unroll
    for (int i = 0; i < 4; i++) {
        int j = lane + 32 * i;
        float ad, am;
        ad = das[j]; am = mas[j];
        float tres = ad * __cosf(dab * dfs[j] + dps[j]) + am * __cosf(mab * mfs[j] + mps[j]);
        float tims = ad * __sinf(dab * dfs[128 + j] + dps[128 + j])
                   + am * __sinf(mab * mfs[128 + j] + mps[128 + j]);
        ad = dao[j]; am = mao[j];
        float treo = ad * __cosf(dab * dfo[j] + dpo[j]) + am * __cosf(mab * mfo[j] + mpo[j]);
        float timo = ad * __sinf(dab * dfo[128 + j] + dpo[128 + j])
                   + am * __sinf(mab * mfo[128 + j] + mpo[128 + j]);
        float cr, sr;
        __sincosf(rr[256 + j] / divc, &sr, &cr);
        float ra = tres * cr - tims * sr - treo;
        float ia = tres * sr + tims * cr - timo;
        sum += sqrtf(ra * ra + ia * ia);
    }

    // sc_rel from precomputed s_rel / o_rel rows
    const float* srp = g_srel + (size_t)(2 * b) * 256;
    const float* orp = g_srel + (size_t)(2 * b + 1) * 256;
    #pragma unroll
    for (int i = 0; i < 4; i++) {
        int j = lane + 32 * i;
        float dre = srp[j] - orp[j];
        float dim = srp[128 + j] - orp[128 + j];
        sum += sqrtf(dre * dre + dim * dim);
    }

    #pragma unroll
    for (int off = 16; off; off >>= 1)
        sum += __shfl_xor_sync(0xffffffffu, sum, off);
    if (lane == 0) out[b] = 12.0f - sum;
}

// ---------------- launch ----------------
extern "C" void kernel_launch(void* const* d_in, const int* in_sizes, int n_in,
                              void* d_out, int out_size) {
    (void)in_sizes; (void)n_in; (void)out_size;
    const void*  x     = d_in[0];
    const float* e_emb = (const float*)d_in[1];
    const float* r_emb = (const float*)d_in[2];
    const float* d_frq = (const float*)d_in[3];
    const float* d_phi = (const float*)d_in[4];
    const float* d_amp = (const float*)d_in[5];
    const float* m_frq = (const float*)d_in[6];
    const float* m_phi = (const float*)d_in[7];
    const float* m_amp = (const float*)d_in[8];
    const float* w_e   = (const float*)d_in[9];
    const float* w_rp  = (const float*)d_in[10];
    float* out = (float*)d_out;

    cudaFuncSetAttribute((const void*)k_rel,
                         cudaFuncAttributeMaxDynamicSharedMemorySize, R_SMEM);

    k_prep<<<1013, 256>>>(x, w_e);
    k_gemm<<<256, 256>>>(x, e_emb);
    k_rel<<<dim3(256, 4), 256, R_SMEM>>>(x, w_rp);
    k_epi<<<1024, 256>>>(x, e_emb, r_emb, d_frq, d_phi, d_amp,
                         m_frq, m_phi, m_amp, out);
}

// round 10
// speedup vs baseline: 1.7124x; 1.7124x over previous
#include <cuda_runtime.h>
#include <cuda_fp16.h>
#include <math.h>

// ---------------- problem constants ----------------
#define XNE   100000
#define XB    8192
#define XCOLS 406

typedef unsigned long long ull;
typedef long long ll;

// ---------------- device scratch ----------------
__device__ int g_xflag;                                  // 1 = x is int64, 0 = int32
__device__ __align__(16) __half g_tab_h[1000 * 256];     // [t][d]: cos | sin halves
__device__ __align__(16) float  g_wp[512 * 256];         // folded e_p_emb weight W'
__device__ __align__(16) float  g_srel[(size_t)XB * 256];// DIFF rows: (s_rel - o_rel)[b][d]

// ---------------- helpers ----------------
__device__ __forceinline__ ll xval(const void* x, int f64, ll i) {
    return f64 ? ((const ll*)x)[i] : (ll)((const int*)x)[i];
}

// ---------------- K_prep: fused (tab | wp | detect) ----------------
__global__ __launch_bounds__(256) void k_prep(const void* __restrict__ x,
                                              const float* __restrict__ w_e) {
    int blk = blockIdx.x;
    int tid = threadIdx.x;
    if (blk < 500) {
        int t = blk * 2 + (tid >> 7);
        int j = tid & 127;
        float ex = (float)(2 * j) / 256.0f;
        float f  = 1.0f / powf(10000.0f, ex);
        float rs = (float)t * f;
        float sv, cv;
        sincosf(rs, &sv, &cv);
        g_tab_h[t * 256 + j]       = __float2half_rn(cv);
        g_tab_h[t * 256 + 128 + j] = __float2half_rn(sv);
    } else if (blk < 1012) {
        int k = blk - 500;
        int j = tid;
        float v;
        if (j < 128) {
            v = w_e[k * 128 + j];
            if (k >= 256) v = -v;
        } else {
            int j2 = j - 128;
            if (k < 256) v = -w_e[(k + 256) * 128 + j2];
            else         v =  w_e[(k - 256) * 128 + j2];
        }
        g_wp[k * 256 + j] = v;
    } else if (tid == 0) {
        const ll* x64 = (const ll*)x;
        int ok = 1;
        for (int i = 0; i < XCOLS; i++) {
            ll v = x64[i];
            if (v < 0 || v >= 100000) { ok = 0; break; }
        }
        g_xflag = ok;
    }
}

// ---------------- K_gemm: P_diff = (E[s]-E[o])(8192x512) @ W'(512x256) ----------------
// 64 b-rows x 256 cols per CTA, 256 threads, 8x8 outputs via packed f32x2 FMA.
// A stored UNduplicated (4 LDS.128/kk total; dup via 1-cyc movs) -> FMA-bound.
__global__ __launch_bounds__(256, 1) void k_gemm(const void* __restrict__ x,
                                                 const float* __restrict__ e_emb) {
    __shared__ __align__(16) float As[16][68];   // 272B row pitch (16-aligned)
    __shared__ __align__(16) float Bs[16][256];
    __shared__ int eidx[128];                    // [0..63]=s idx, [64..127]=o idx

    int tid = threadIdx.x;
    int m0  = blockIdx.x * 64;
    if (tid < 128) {
        int b = m0 + (tid & 63);
        eidx[tid] = (int)xval(x, g_xflag, (ll)b * XCOLS + ((tid < 64) ? 0 : 2));
    }
    __syncthreads();

    int ty = tid >> 5, tx = tid & 31;
    ull acc[8][4];
    #pragma unroll
    for (int r = 0; r < 8; r++)
        #pragma unroll
        for (int c = 0; c < 4; c++) acc[r][c] = 0ULL;

    int arow = tid >> 2, acg = (tid & 3) << 2;
    const float* asrc_s = e_emb + (size_t)eidx[arow] * 512 + acg;
    const float* asrc_o = e_emb + (size_t)eidx[64 + arow] * 512 + acg;
    int bkr = tid >> 4, bcol = (tid & 15) << 4;

    for (int k0 = 0; k0 < 512; k0 += 16) {
        float4 s4 = *(const float4*)(asrc_s + k0);
        float4 o4 = *(const float4*)(asrc_o + k0);
        As[acg + 0][arow] = s4.x - o4.x;
        As[acg + 1][arow] = s4.y - o4.y;
        As[acg + 2][arow] = s4.z - o4.z;
        As[acg + 3][arow] = s4.w - o4.w;

        const float* bsrc = g_wp + (size_t)(k0 + bkr) * 256 + bcol;
        *(float4*)&Bs[bkr][bcol + 0]  = *(const float4*)(bsrc + 0);
        *(float4*)&Bs[bkr][bcol + 4]  = *(const float4*)(bsrc + 4);
        *(float4*)&Bs[bkr][bcol + 8]  = *(const float4*)(bsrc + 8);
        *(float4*)&Bs[bkr][bcol + 12] = *(const float4*)(bsrc + 12);
        __syncthreads();

        #pragma unroll
        for (int kk = 0; kk < 16; kk++) {
            float4 a03 = *(const float4*)&As[kk][ty * 8 + 0];
            float4 a47 = *(const float4*)&As[kk][ty * 8 + 4];
            ull a_[8];
            asm("mov.b64 %0, {%1,%1};" : "=l"(a_[0]) : "f"(a03.x));
            asm("mov.b64 %0, {%1,%1};" : "=l"(a_[1]) : "f"(a03.y));
            asm("mov.b64 %0, {%1,%1};" : "=l"(a_[2]) : "f"(a03.z));
            asm("mov.b64 %0, {%1,%1};" : "=l"(a_[3]) : "f"(a03.w));
            asm("mov.b64 %0, {%1,%1};" : "=l"(a_[4]) : "f"(a47.x));
            asm("mov.b64 %0, {%1,%1};" : "=l"(a_[5]) : "f"(a47.y));
            asm("mov.b64 %0, {%1,%1};" : "=l"(a_[6]) : "f"(a47.z));
            asm("mov.b64 %0, {%1,%1};" : "=l"(a_[7]) : "f"(a47.w));
            ulonglong2 b01 = *(const ulonglong2*)&Bs[kk][tx * 4];
            ulonglong2 b23 = *(const ulonglong2*)&Bs[kk][128 + tx * 4];
            ull b_[4] = {b01.x, b01.y, b23.x, b23.y};
            #pragma unroll
            for (int r = 0; r < 8; r++)
                #pragma unroll
                for (int c = 0; c < 4; c++)
                    asm("fma.rn.f32x2 %0, %1, %2, %0;"
                        : "+l"(acc[r][c]) : "l"(a_[r]), "l"(b_[c]));
        }
        __syncthreads();
    }

    #pragma unroll
    for (int r = 0; r < 8; r++) {
        float y0, y1, y2, y3;
        asm("mov.b64 {%0,%1}, %2;" : "=f"(y0), "=f"(y1) : "l"(acc[r][0]));
        asm("mov.b64 {%0,%1}, %2;" : "=f"(y2), "=f"(y3) : "l"(acc[r][1]));
        float* dst = g_srel + (size_t)(m0 + ty * 8 + r) * 256 + tx * 4;
        *(float4*)dst = make_float4(y0, y1, y2, y3);
        asm("mov.b64 {%0,%1}, %2;" : "=f"(y0), "=f"(y1) : "l"(acc[r][2]));
        asm("mov.b64 {%0,%1}, %2;" : "=f"(y2), "=f"(y3) : "l"(acc[r][3]));
        *(float4*)(dst + 128) = make_float4(y0, y1, y2, y3);
    }
}

// ---------------- K_rel: g_srel += sum_n w[n]*(TAB[t_s]-TAB[t_o]) ----------------
// Grid (128, 4), 512 threads (16 warps): 64 b x 64-d slice per CTA.
// Coeff packed: u32 (t_s | t_o<<16) + fp16 weight. 2x LDS.128 + 4 HSUB2 per 8 d.
#define R_SMEM (144000 + 51200 + 25600)
__global__ __launch_bounds__(512) void k_rel(const void* __restrict__ x,
                                             const float* __restrict__ w_rp) {
    extern __shared__ __align__(16) char sm4[];
    __half*       tab_s = (__half*)sm4;                       // 1000 x 72 halves
    unsigned int* cpk   = (unsigned int*)(sm4 + 144000);      // 64 x 200: ts|to<<16
    __half*       whv   = (__half*)(sm4 + 144000 + 51200);    // 64 x 200 weights
    __shared__ int ritem[64];

    int tid = threadIdx.x;
    int f64 = g_xflag;
    int i0  = blockIdx.x * 64;
    int d0  = blockIdx.y * 64;

    for (int idx = tid; idx < 8000; idx += 512) {
        int row = idx >> 3, seg = idx & 7;
        *(uint4*)(tab_s + row * 72 + seg * 8) =
            *(const uint4*)(g_tab_h + row * 256 + d0 + seg * 8);
    }
    if (tid < 64)
        ritem[tid] = (int)xval(x, f64, (ll)(i0 + tid) * XCOLS + 1);
    __syncthreads();

    for (int idx = tid; idx < 12800; idx += 512) {
        int it = idx / 200, n = idx - it * 200;
        int b = i0 + it;
        unsigned int ts = (unsigned int)xval(x, f64, (ll)b * XCOLS + 6 + n);
        unsigned int to = (unsigned int)xval(x, f64, (ll)b * XCOLS + 206 + n);
        cpk[idx] = ts | (to << 16);
        whv[idx] = __float2half(w_rp[ritem[it] * 200 + n]);
    }
    __syncthreads();

    int lane = tid & 31, w = tid >> 5;
    int item = w * 4 + (lane >> 3);   // 0..63
    int dg   = lane & 7;
    const unsigned int* cp = cpk + item * 200;
    const __half*       wp = whv + item * 200;
    const __half*       tb = tab_s + dg * 8;

    float acc[8] = {0.f, 0.f, 0.f, 0.f, 0.f, 0.f, 0.f, 0.f};
    #pragma unroll 4
    for (int n = 0; n < 200; n++) {
        unsigned int pk = cp[n];
        float wn = __half2float(wp[n]);
        unsigned int ts = pk & 0xFFFFu, to = pk >> 16;
        uint4 hs = *(const uint4*)(tb + (size_t)ts * 72);
        uint4 ho = *(const uint4*)(tb + (size_t)to * 72);
        __half2 d0h = __hsub2(*(__half2*)&hs.x, *(__half2*)&ho.x);
        __half2 d1h = __hsub2(*(__half2*)&hs.y, *(__half2*)&ho.y);
        __half2 d2h = __hsub2(*(__half2*)&hs.z, *(__half2*)&ho.z);
        __half2 d3h = __hsub2(*(__half2*)&hs.w, *(__half2*)&ho.w);
        float2 v0 = __half22float2(d0h);
        float2 v1 = __half22float2(d1h);
        float2 v2 = __half22float2(d2h);
        float2 v3 = __half22float2(d3h);
        acc[0] = fmaf(v0.x, wn, acc[0]); acc[1] = fmaf(v0.y, wn, acc[1]);
        acc[2] = fmaf(v1.x, wn, acc[2]); acc[3] = fmaf(v1.y, wn, acc[3]);
        acc[4] = fmaf(v2.x, wn, acc[4]); acc[5] = fmaf(v2.y, wn, acc[5]);
        acc[6] = fmaf(v3.x, wn, acc[6]); acc[7] = fmaf(v3.y, wn, acc[7]);
    }

    float* dst = g_srel + (size_t)(i0 + item) * 256 + d0 + dg * 8;
    float4 o0 = *(float4*)dst;
    o0.x += acc[0]; o0.y += acc[1]; o0.z += acc[2]; o0.w += acc[3];
    *(float4*)dst = o0;
    float4 o1 = *(float4*)(dst + 4);
    o1.x += acc[4]; o1.y += acc[5]; o1.z += acc[6]; o1.w += acc[7];
    *(float4*)(dst + 4) = o1;
}

// ---------------- K_epi: sc_abs (inline t_emb) + sc_rel from diff rows ----------------
__global__ __launch_bounds__(256) void k_epi(const void* __restrict__ x,
        const float* __restrict__ e_emb, const float* __restrict__ r_emb,
        const float* __restrict__ d_frq, const float* __restrict__ d_phi,
        const float* __restrict__ d_amp, const float* __restrict__ m_frq,
        const float* __restrict__ m_phi, const float* __restrict__ m_amp,
        float* __restrict__ out) {
    int lane = threadIdx.x & 31;
    int b = blockIdx.x * 8 + (threadIdx.x >> 5);
    int f64 = g_xflag;
    ll base = (ll)b * XCOLS;
    int s = (int)xval(x, f64, base + 0);
    int r = (int)xval(x, f64, base + 1);
    int o = (int)xval(x, f64, base + 2);
    float dab = (float)xval(x, f64, base + 3);
    float mab = (float)xval(x, f64, base + 4);

    float divc = (float)(sqrt(6.0 / 584.0) / 3.141592653589793);

    const float* es = e_emb + (size_t)s * 512;
    const float* eo = e_emb + (size_t)o * 512;
    const float* rr = r_emb + (size_t)r * 384;

    float sum = 0.f;

    #pragma unroll
    for (int i = 0; i < 8; i++) {
        int dd = lane + 32 * i;
        float res = es[dd], ims = es[256 + dd];
        float reo = eo[dd], imo = eo[256 + dd];
        float cr, sr;
        __sincosf(rr[dd] / divc, &sr, &cr);
        float ra = res * cr - ims * sr - reo;
        float ia = res * sr + ims * cr - imo;
        sum += sqrtf(ra * ra + ia * ia);
    }

    const float* dfs = d_frq + (size_t)s * 256; const float* dps = d_phi + (size_t)s * 256;
    const float* das = d_amp + (size_t)s * 128;
    const float* mfs = m_frq + (size_t)s * 256; const float* mps = m_phi + (size_t)s * 256;
    const float* mas = m_amp + (size_t)s * 128;
    const float* dfo = d_frq + (size_t)o * 256; const float* dpo = d_phi + (size_t)o * 256;
    const float* dao = d_amp + (size_t)o * 128;
    const float* mfo = m_frq + (size_t)o * 256; const float* mpo = m_phi + (size_t)o * 256;
    const float* mao = m_amp + (size_t)o * 128;
    #pragma unroll
    for (int i = 0; i < 4; i++) {
        int j = lane + 32 * i;
        float ad, am;
        ad = das[j]; am = mas[j];
        float tres = ad * __cosf(dab * dfs[j] + dps[j]) + am * __cosf(mab * mfs[j] + mps[j]);
        float tims = ad * __sinf(dab * dfs[128 + j] + dps[128 + j])
                   + am * __sinf(mab * mfs[128 + j] + mps[128 + j]);
        ad = dao[j]; am = mao[j];
        float treo = ad * __cosf(dab * dfo[j] + dpo[j]) + am * __cosf(mab * mfo[j] + mpo[j]);
        float timo = ad * __sinf(dab * dfo[128 + j] + dpo[128 + j])
                   + am * __sinf(mab * mfo[128 + j] + mpo[128 + j]);
        float cr, sr;
        __sincosf(rr[256 + j] / divc, &sr, &cr);
        float ra = tres * cr - tims * sr - treo;
        float ia = tres * sr + tims * cr - timo;
        sum += sqrtf(ra * ra + ia * ia);
    }

    // sc_rel from precomputed DIFF rows
    const float* srd = g_srel + (size_t)b * 256;
    #pragma unroll
    for (int i = 0; i < 4; i++) {
        int j = lane + 32 * i;
        float dre = srd[j];
        float dim = srd[128 + j];
        sum += sqrtf(dre * dre + dim * dim);
    }

    #pragma unroll
    for (int off = 16; off; off >>= 1)
        sum += __shfl_xor_sync(0xffffffffu, sum, off);
    if (lane == 0) out[b] = 12.0f - sum;
}

// ---------------- launch ----------------
extern "C" void kernel_launch(void* const* d_in, const int* in_sizes, int n_in,
                              void* d_out, int out_size) {
    (void)in_sizes; (void)n_in; (void)out_size;
    const void*  x     = d_in[0];
    const float* e_emb = (const float*)d_in[1];
    const float* r_emb = (const float*)d_in[2];
    const float* d_frq = (const float*)d_in[3];
    const float* d_phi = (const float*)d_in[4];
    const float* d_amp = (const float*)d_in[5];
    const float* m_frq = (const float*)d_in[6];
    const float* m_phi = (const float*)d_in[7];
    const float* m_amp = (const float*)d_in[8];
    const float* w_e   = (const float*)d_in[9];
    const float* w_rp  = (const float*)d_in[10];
    float* out = (float*)d_out;

    cudaFuncSetAttribute((const void*)k_rel,
                         cudaFuncAttributeMaxDynamicSharedMemorySize, R_SMEM);

    k_prep<<<1013, 256>>>(x, w_e);
    k_gemm<<<128, 256>>>(x, e_emb);
    k_rel<<<dim3(128, 4), 512, R_SMEM>>>(x, w_rp);
    k_epi<<<1024, 256>>>(x, e_emb, r_emb, d_frq, d_phi, d_amp,
                         m_frq, m_phi, m_amp, out);
}

// round 12
// speedup vs baseline: 1.8313x; 1.0694x over previous
#include <cuda_runtime.h>
#include <cuda_fp16.h>
#include <math.h>

// ---------------- problem constants ----------------
#define XNE   100000
#define XB    8192
#define XCOLS 406

typedef unsigned long long ull;
typedef long long ll;

// ---------------- device scratch ----------------
__device__ int g_xflag;                                  // 1 = x is int64, 0 = int32
__device__ __align__(16) __half g_tab_h[1000 * 256];     // [t][d]: cos | sin halves
__device__ __align__(16) float  g_wp[512 * 256];         // folded e_p_emb weight W'
__device__ __align__(16) float  g_srel[(size_t)XB * 256];// DIFF rows: (s_rel - o_rel)[b][d]

// ---------------- helpers ----------------
__device__ __forceinline__ ll xval(const void* x, int f64, ll i) {
    return f64 ? ((const ll*)x)[i] : (ll)((const int*)x)[i];
}

// ---------------- K_prep: fused (tab | wp | detect) ----------------
__global__ __launch_bounds__(256) void k_prep(const void* __restrict__ x,
                                              const float* __restrict__ w_e) {
    int blk = blockIdx.x;
    int tid = threadIdx.x;
    if (blk < 500) {
        int t = blk * 2 + (tid >> 7);
        int j = tid & 127;
        float ex = (float)(2 * j) / 256.0f;
        float f  = 1.0f / powf(10000.0f, ex);
        float rs = (float)t * f;
        float sv, cv;
        sincosf(rs, &sv, &cv);
        g_tab_h[t * 256 + j]       = __float2half_rn(cv);
        g_tab_h[t * 256 + 128 + j] = __float2half_rn(sv);
    } else if (blk < 1012) {
        int k = blk - 500;
        int j = tid;
        float v;
        if (j < 128) {
            v = w_e[k * 128 + j];
            if (k >= 256) v = -v;
        } else {
            int j2 = j - 128;
            if (k < 256) v = -w_e[(k + 256) * 128 + j2];
            else         v =  w_e[(k - 256) * 128 + j2];
        }
        g_wp[k * 256 + j] = v;
    } else {
        // PARALLEL width probe: 256 threads x 2 independent loads (no serial
        // chain — the old 1-thread early-exit loop was a ~100us pointer-chase).
        __shared__ int bad;
        if (tid == 0) bad = 0;
        __syncthreads();
        const ll* x64 = (const ll*)x;
        int mybad = 0;
        #pragma unroll
        for (int k = 0; k < 2; k++) {
            int i = tid * 2 + k;
            if (i < XCOLS) {
                ll v = x64[i];
                if (v < 0 || v >= 100000) mybad = 1;
            }
        }
        if (mybad) bad = 1;
        __syncthreads();
        if (tid == 0) g_xflag = bad ? 0 : 1;
    }
}

// ---------------- K_gemm: P_diff = (E[s]-E[o])(8192x512) @ W'(512x256) ----------------
// 64 b-rows x 256 cols per CTA, 256 threads, 8x8 outputs via packed f32x2 FMA.
// Register double-buffering: next tile's gathered A + B prefetched right after
// the barrier so LDG latency hides under the FMA phase.
__global__ __launch_bounds__(256, 1) void k_gemm(const void* __restrict__ x,
                                                 const float* __restrict__ e_emb) {
    __shared__ __align__(16) float As[16][68];   // 272B row pitch (16-aligned)
    __shared__ __align__(16) float Bs[16][256];
    __shared__ int eidx[128];                    // [0..63]=s idx, [64..127]=o idx

    int tid = threadIdx.x;
    int m0  = blockIdx.x * 64;
    if (tid < 128) {
        int b = m0 + (tid & 63);
        eidx[tid] = (int)xval(x, g_xflag, (ll)b * XCOLS + ((tid < 64) ? 0 : 2));
    }
    __syncthreads();

    int ty = tid >> 5, tx = tid & 31;
    ull acc[8][4];
    #pragma unroll
    for (int r = 0; r < 8; r++)
        #pragma unroll
        for (int c = 0; c < 4; c++) acc[r][c] = 0ULL;

    int arow = tid >> 2, acg = (tid & 3) << 2;
    const float* asrc_s = e_emb + (size_t)eidx[arow] * 512 + acg;
    const float* asrc_o = e_emb + (size_t)eidx[64 + arow] * 512 + acg;
    int bkr = tid >> 4, bcol = (tid & 15) << 4;
    const float* bbase = g_wp + (size_t)bkr * 256 + bcol;

    // prefetch tile 0
    float4 s4 = *(const float4*)(asrc_s);
    float4 o4 = *(const float4*)(asrc_o);
    float4 b0 = *(const float4*)(bbase + 0);
    float4 b1 = *(const float4*)(bbase + 4);
    float4 b2 = *(const float4*)(bbase + 8);
    float4 b3 = *(const float4*)(bbase + 12);

    for (int k0 = 0; k0 < 512; k0 += 16) {
        As[acg + 0][arow] = s4.x - o4.x;
        As[acg + 1][arow] = s4.y - o4.y;
        As[acg + 2][arow] = s4.z - o4.z;
        As[acg + 3][arow] = s4.w - o4.w;
        *(float4*)&Bs[bkr][bcol + 0]  = b0;
        *(float4*)&Bs[bkr][bcol + 4]  = b1;
        *(float4*)&Bs[bkr][bcol + 8]  = b2;
        *(float4*)&Bs[bkr][bcol + 12] = b3;
        __syncthreads();

        if (k0 + 16 < 512) {   // prefetch next tile (latency hidden by compute)
            s4 = *(const float4*)(asrc_s + k0 + 16);
            o4 = *(const float4*)(asrc_o + k0 + 16);
            const float* bn = bbase + (size_t)(k0 + 16) * 256;
            b0 = *(const float4*)(bn + 0);
            b1 = *(const float4*)(bn + 4);
            b2 = *(const float4*)(bn + 8);
            b3 = *(const float4*)(bn + 12);
        }

        #pragma unroll
        for (int kk = 0; kk < 16; kk++) {
            float4 a03 = *(const float4*)&As[kk][ty * 8 + 0];
            float4 a47 = *(const float4*)&As[kk][ty * 8 + 4];
            ull a_[8];
            asm("mov.b64 %0, {%1,%1};" : "=l"(a_[0]) : "f"(a03.x));
            asm("mov.b64 %0, {%1,%1};" : "=l"(a_[1]) : "f"(a03.y));
            asm("mov.b64 %0, {%1,%1};" : "=l"(a_[2]) : "f"(a03.z));
            asm("mov.b64 %0, {%1,%1};" : "=l"(a_[3]) : "f"(a03.w));
            asm("mov.b64 %0, {%1,%1};" : "=l"(a_[4]) : "f"(a47.x));
            asm("mov.b64 %0, {%1,%1};" : "=l"(a_[5]) : "f"(a47.y));
            asm("mov.b64 %0, {%1,%1};" : "=l"(a_[6]) : "f"(a47.z));
            asm("mov.b64 %0, {%1,%1};" : "=l"(a_[7]) : "f"(a47.w));
            ulonglong2 bb01 = *(const ulonglong2*)&Bs[kk][tx * 4];
            ulonglong2 bb23 = *(const ulonglong2*)&Bs[kk][128 + tx * 4];
            ull b_[4] = {bb01.x, bb01.y, bb23.x, bb23.y};
            #pragma unroll
            for (int r = 0; r < 8; r++)
                #pragma unroll
                for (int c = 0; c < 4; c++)
                    asm("fma.rn.f32x2 %0, %1, %2, %0;"
                        : "+l"(acc[r][c]) : "l"(a_[r]), "l"(b_[c]));
        }
        __syncthreads();
    }

    #pragma unroll
    for (int r = 0; r < 8; r++) {
        float y0, y1, y2, y3;
        asm("mov.b64 {%0,%1}, %2;" : "=f"(y0), "=f"(y1) : "l"(acc[r][0]));
        asm("mov.b64 {%0,%1}, %2;" : "=f"(y2), "=f"(y3) : "l"(acc[r][1]));
        float* dst = g_srel + (size_t)(m0 + ty * 8 + r) * 256 + tx * 4;
        *(float4*)dst = make_float4(y0, y1, y2, y3);
        asm("mov.b64 {%0,%1}, %2;" : "=f"(y0), "=f"(y1) : "l"(acc[r][2]));
        asm("mov.b64 {%0,%1}, %2;" : "=f"(y2), "=f"(y3) : "l"(acc[r][3]));
        *(float4*)(dst + 128) = make_float4(y0, y1, y2, y3);
    }
}

// ---------------- K_rel: g_srel += sum_n w[n]*(TAB[t_s]-TAB[t_o]) ----------------
// Grid (128, 4), 512 threads (16 warps): 64 b x 64-d slice per CTA.
// Coeff packed: u32 (t_s | t_o<<16) + fp16 weight. 2x LDS.128 + 4 HSUB2 per 8 d.
#define R_SMEM (144000 + 51200 + 25600)
__global__ __launch_bounds__(512) void k_rel(const void* __restrict__ x,
                                             const float* __restrict__ w_rp) {
    extern __shared__ __align__(16) char sm4[];
    __half*       tab_s = (__half*)sm4;                       // 1000 x 72 halves
    unsigned int* cpk   = (unsigned int*)(sm4 + 144000);      // 64 x 200: ts|to<<16
    __half*       whv   = (__half*)(sm4 + 144000 + 51200);    // 64 x 200 weights
    __shared__ int ritem[64];

    int tid = threadIdx.x;
    int f64 = g_xflag;
    int i0  = blockIdx.x * 64;
    int d0  = blockIdx.y * 64;

    for (int idx = tid; idx < 8000; idx += 512) {
        int row = idx >> 3, seg = idx & 7;
        *(uint4*)(tab_s + row * 72 + seg * 8) =
            *(const uint4*)(g_tab_h + row * 256 + d0 + seg * 8);
    }
    if (tid < 64)
        ritem[tid] = (int)xval(x, f64, (ll)(i0 + tid) * XCOLS + 1);
    __syncthreads();

    for (int idx = tid; idx < 12800; idx += 512) {
        int it = idx / 200, n = idx - it * 200;
        int b = i0 + it;
        unsigned int ts = (unsigned int)xval(x, f64, (ll)b * XCOLS + 6 + n);
        unsigned int to = (unsigned int)xval(x, f64, (ll)b * XCOLS + 206 + n);
        cpk[idx] = ts | (to << 16);
        whv[idx] = __float2half(w_rp[ritem[it] * 200 + n]);
    }
    __syncthreads();

    int lane = tid & 31, w = tid >> 5;
    int item = w * 4 + (lane >> 3);   // 0..63
    int dg   = lane & 7;
    const unsigned int* cp = cpk + item * 200;
    const __half*       wp = whv + item * 200;
    const __half*       tb = tab_s + dg * 8;

    float acc[8] = {0.f, 0.f, 0.f, 0.f, 0.f, 0.f, 0.f, 0.f};
    #pragma unroll 4
    for (int n = 0; n < 200; n++) {
        unsigned int pk = cp[n];
        float wn = __half2float(wp[n]);
        unsigned int ts = pk & 0xFFFFu, to = pk >> 16;
        uint4 hs = *(const uint4*)(tb + (size_t)ts * 72);
        uint4 ho = *(const uint4*)(tb + (size_t)to * 72);
        __half2 d0h = __hsub2(*(__half2*)&hs.x, *(__half2*)&ho.x);
        __half2 d1h = __hsub2(*(__half2*)&hs.y, *(__half2*)&ho.y);
        __half2 d2h = __hsub2(*(__half2*)&hs.z, *(__half2*)&ho.z);
        __half2 d3h = __hsub2(*(__half2*)&hs.w, *(__half2*)&ho.w);
        float2 v0 = __half22float2(d0h);
        float2 v1 = __half22float2(d1h);
        float2 v2 = __half22float2(d2h);
        float2 v3 = __half22float2(d3h);
        acc[0] = fmaf(v0.x, wn, acc[0]); acc[1] = fmaf(v0.y, wn, acc[1]);
        acc[2] = fmaf(v1.x, wn, acc[2]); acc[3] = fmaf(v1.y, wn, acc[3]);
        acc[4] = fmaf(v2.x, wn, acc[4]); acc[5] = fmaf(v2.y, wn, acc[5]);
        acc[6] = fmaf(v3.x, wn, acc[6]); acc[7] = fmaf(v3.y, wn, acc[7]);
    }

    float* dst = g_srel + (size_t)(i0 + item) * 256 + d0 + dg * 8;
    float4 o0 = *(float4*)dst;
    o0.x += acc[0]; o0.y += acc[1]; o0.z += acc[2]; o0.w += acc[3];
    *(float4*)dst = o0;
    float4 o1 = *(float4*)(dst + 4);
    o1.x += acc[4]; o1.y += acc[5]; o1.z += acc[6]; o1.w += acc[7];
    *(float4*)(dst + 4) = o1;
}

// ---------------- K_epi: sc_abs (inline t_emb) + sc_rel from diff rows ----------------
__global__ __launch_bounds__(256) void k_epi(const void* __restrict__ x,
        const float* __restrict__ e_emb, const float* __restrict__ r_emb,
        const float* __restrict__ d_frq, const float* __restrict__ d_phi,
        const float* __restrict__ d_amp, const float* __restrict__ m_frq,
        const float* __restrict__ m_phi, const float* __restrict__ m_amp,
        float* __restrict__ out) {
    int lane = threadIdx.x & 31;
    int b = blockIdx.x * 8 + (threadIdx.x >> 5);
    int f64 = g_xflag;
    ll base = (ll)b * XCOLS;
    int s = (int)xval(x, f64, base + 0);
    int r = (int)xval(x, f64, base + 1);
    int o = (int)xval(x, f64, base + 2);
    float dab = (float)xval(x, f64, base + 3);
    float mab = (float)xval(x, f64, base + 4);

    float divc = (float)(sqrt(6.0 / 584.0) / 3.141592653589793);

    const float* es = e_emb + (size_t)s * 512;
    const float* eo = e_emb + (size_t)o * 512;
    const float* rr = r_emb + (size_t)r * 384;

    float sum = 0.f;

    #pragma unroll
    for (int i = 0; i < 8; i++) {
        int dd = lane + 32 * i;
        float res = es[dd], ims = es[256 + dd];
        float reo = eo[dd], imo = eo[256 + dd];
        float cr, sr;
        __sincosf(rr[dd] / divc, &sr, &cr);
        float ra = res * cr - ims * sr - reo;
        float ia = res * sr + ims * cr - imo;
        sum += sqrtf(ra * ra + ia * ia);
    }

    const float* dfs = d_frq + (size_t)s * 256; const float* dps = d_phi + (size_t)s * 256;
    const float* das = d_amp + (size_t)s * 128;
    const float* mfs = m_frq + (size_t)s * 256; const float* mps = m_phi + (size_t)s * 256;
    const float* mas = m_amp + (size_t)s * 128;
    const float* dfo = d_frq + (size_t)o * 256; const float* dpo = d_phi + (size_t)o * 256;
    const float* dao = d_amp + (size_t)o * 128;
    const float* mfo = m_frq + (size_t)o * 256; const float* mpo = m_phi + (size_t)o * 256;
    const float* mao = m_amp + (size_t)o * 128;
    #pragma unroll
    for (int i = 0; i < 4; i++) {
        int j = lane + 32 * i;
        float ad, am;
        ad = das[j]; am = mas[j];
        float tres = ad * __cosf(dab * dfs[j] + dps[j]) + am * __cosf(mab * mfs[j] + mps[j]);
        float tims = ad * __sinf(dab * dfs[128 + j] + dps[128 + j])
                   + am * __sinf(mab * mfs[128 + j] + mps[128 + j]);
        ad = dao[j]; am = mao[j];
        float treo = ad * __cosf(dab * dfo[j] + dpo[j]) + am * __cosf(mab * mfo[j] + mpo[j]);
        float timo = ad * __sinf(dab * dfo[128 + j] + dpo[128 + j])
                   + am * __sinf(mab * mfo[128 + j] + mpo[128 + j]);
        float cr, sr;
        __sincosf(rr[256 + j] / divc, &sr, &cr);
        float ra = tres * cr - tims * sr - treo;
        float ia = tres * sr + tims * cr - timo;
        sum += sqrtf(ra * ra + ia * ia);
    }

    // sc_rel from precomputed DIFF rows
    const float* srd = g_srel + (size_t)b * 256;
    #pragma unroll
    for (int i = 0; i < 4; i++) {
        int j = lane + 32 * i;
        float dre = srd[j];
        float dim = srd[128 + j];
        sum += sqrtf(dre * dre + dim * dim);
    }

    #pragma unroll
    for (int off = 16; off; off >>= 1)
        sum += __shfl_xor_sync(0xffffffffu, sum, off);
    if (lane == 0) out[b] = 12.0f - sum;
}

// ---------------- launch ----------------
extern "C" void kernel_launch(void* const* d_in, const int* in_sizes, int n_in,
                              void* d_out, int out_size) {
    (void)in_sizes; (void)n_in; (void)out_size;
    const void*  x     = d_in[0];
    const float* e_emb = (const float*)d_in[1];
    const float* r_emb = (const float*)d_in[2];
    const float* d_frq = (const float*)d_in[3];
    const float* d_phi = (const float*)d_in[4];
    const float* d_amp = (const float*)d_in[5];
    const float* m_frq = (const float*)d_in[6];
    const float* m_phi = (const float*)d_in[7];
    const float* m_amp = (const float*)d_in[8];
    const float* w_e   = (const float*)d_in[9];
    const float* w_rp  = (const float*)d_in[10];
    float* out = (float*)d_out;

    cudaFuncSetAttribute((const void*)k_rel,
                         cudaFuncAttributeMaxDynamicSharedMemorySize, R_SMEM);

    k_prep<<<1013, 256>>>(x, w_e);
    k_gemm<<<128, 256>>>(x, e_emb);
    k_rel<<<dim3(128, 4), 512, R_SMEM>>>(x, w_rp);
    k_epi<<<1024, 256>>>(x, e_emb, r_emb, d_frq, d_phi, d_amp,
                         m_frq, m_phi, m_amp, out);
}